// round 1
// baseline (speedup 1.0000x reference)
#include <cuda_runtime.h>
#include <math.h>

#define N_NODES 100000
#define N_EDGES 1600000
#define ETOT    (N_EDGES + N_NODES)
#define IN_DIM  256
#define HID     128
#define OUTD    64
#define NEG_SLOPE 0.2f
#define SCAN_NB ((N_NODES + 255) / 256)   // 391

// ---------------- scratch (static device globals; no allocation) ----------------
static __device__ __align__(128) float g_h1[(size_t)N_NODES * HID];   // x@W1
static __device__ __align__(128) float g_o1[(size_t)N_NODES * HID];   // elu(agg1 + b1)
static __device__ __align__(128) float g_h2[(size_t)N_NODES * OUTD];  // o1@W2
static __device__ float g_ssrc[N_NODES];
static __device__ float g_sdst[N_NODES];
static __device__ int   g_cnt[N_NODES];
static __device__ int   g_cur[N_NODES];
static __device__ int   g_off[N_NODES + 1];
static __device__ int   g_bsum[512];
static __device__ int   g_col[ETOT];
static __device__ int   g_slot[ETOT];
static __device__ float g_eval[ETOT];

// ---------------- CSR build ----------------
__global__ void k_zero() {
    int i = blockIdx.x * blockDim.x + threadIdx.x;
    if (i < N_NODES) { g_cnt[i] = 0; g_cur[i] = 0; }
}

__global__ void k_count(const int* __restrict__ ei) {
    int t = blockIdx.x * blockDim.x + threadIdx.x;
    if (t >= ETOT) return;
    int dst = (t < N_EDGES) ? ei[N_EDGES + t] : (t - N_EDGES);
    atomicAdd(&g_cnt[dst], 1);
}

__global__ void k_scan1() {
    __shared__ int s[256];
    int t = threadIdx.x, idx = blockIdx.x * 256 + t;
    int v = (idx < N_NODES) ? g_cnt[idx] : 0;
    s[t] = v; __syncthreads();
    #pragma unroll
    for (int o = 1; o < 256; o <<= 1) {
        int u = (t >= o) ? s[t - o] : 0;
        __syncthreads();
        s[t] += u;
        __syncthreads();
    }
    if (idx < N_NODES) g_off[idx] = s[t] - v;   // exclusive within block
    if (t == 255) g_bsum[blockIdx.x] = s[t];
}

__global__ void k_scan2(int nb) {
    __shared__ int s[512];
    int t = threadIdx.x;
    int v = (t < nb) ? g_bsum[t] : 0;
    s[t] = v; __syncthreads();
    #pragma unroll
    for (int o = 1; o < 512; o <<= 1) {
        int u = (t >= o) ? s[t - o] : 0;
        __syncthreads();
        s[t] += u;
        __syncthreads();
    }
    g_bsum[t] = s[t] - v;                       // exclusive block offsets
}

__global__ void k_scan3() {
    int t = threadIdx.x, idx = blockIdx.x * 256 + t;
    if (idx < N_NODES) g_off[idx] += g_bsum[blockIdx.x];
    if (idx == 0) g_off[N_NODES] = ETOT;
}

// ---------------- GEMM: C[M,NCOL] = A[M,K] @ W[K,NCOL], fp32 ----------------
template<int K, int NCOL>
__global__ void k_gemm(const float* __restrict__ A, const float* __restrict__ W,
                       float* __restrict__ C, int M) {
    constexpr int BM = 64, BK = 16, TM = 4, TN = NCOL / 16, NC4 = NCOL / 4;
    __shared__ float As[BM][BK];
    __shared__ float Ws[BK][NCOL];
    const int tid = threadIdx.x;
    const int tc = tid & 15;       // 16 col groups
    const int tr = tid >> 4;       // 16 row groups
    const int m0 = blockIdx.x * BM;
    const int arow = tid >> 2, ac4 = (tid & 3) * 4;

    float acc[TM][TN];
    #pragma unroll
    for (int r = 0; r < TM; r++)
        #pragma unroll
        for (int n = 0; n < TN; n++) acc[r][n] = 0.f;

    for (int k0 = 0; k0 < K; k0 += BK) {
        float4 av = make_float4(0.f, 0.f, 0.f, 0.f);
        if (m0 + arow < M)
            av = *(const float4*)(A + (size_t)(m0 + arow) * K + k0 + ac4);
        *(float4*)&As[arow][ac4] = av;
        #pragma unroll
        for (int i = tid; i < BK * NC4; i += 256) {
            int wr = i / NC4, wc = i % NC4;
            *(float4*)&Ws[wr][wc * 4] = *(const float4*)(W + (size_t)(k0 + wr) * NCOL + wc * 4);
        }
        __syncthreads();
        #pragma unroll
        for (int kk = 0; kk < BK; kk++) {
            float a_[TM], w_[TN];
            #pragma unroll
            for (int r = 0; r < TM; r++) a_[r] = As[tr * TM + r][kk];
            #pragma unroll
            for (int n = 0; n < TN; n++) w_[n] = Ws[kk][tc * TN + n];
            #pragma unroll
            for (int r = 0; r < TM; r++)
                #pragma unroll
                for (int n = 0; n < TN; n++)
                    acc[r][n] = fmaf(a_[r], w_[n], acc[r][n]);
        }
        __syncthreads();
    }

    #pragma unroll
    for (int r = 0; r < TM; r++) {
        int row = m0 + tr * TM + r;
        if (row < M) {
            #pragma unroll
            for (int n = 0; n < TN; n += 4) {
                float4 v = make_float4(acc[r][n], acc[r][n + 1], acc[r][n + 2], acc[r][n + 3]);
                *(float4*)(C + (size_t)row * NCOL + tc * TN + n) = v;
            }
        }
    }
}

// ---------------- per-node attention scores s_src, s_dst ----------------
template<int F>
__global__ void k_sdot(const float* __restrict__ h, const float* __restrict__ asrc,
                       const float* __restrict__ adst) {
    int node = (blockIdx.x * blockDim.x + threadIdx.x) >> 5;
    if (node >= N_NODES) return;
    int lane = threadIdx.x & 31;
    float d1 = 0.f, d2 = 0.f;
    if (F == 128) {
        float4 hv = *(const float4*)(h + (size_t)node * 128 + lane * 4);
        float4 a1 = *(const float4*)(asrc + lane * 4);
        float4 a2 = *(const float4*)(adst + lane * 4);
        d1 = hv.x * a1.x + hv.y * a1.y + hv.z * a1.z + hv.w * a1.w;
        d2 = hv.x * a2.x + hv.y * a2.y + hv.z * a2.z + hv.w * a2.w;
    } else {
        float2 hv = *(const float2*)(h + (size_t)node * 64 + lane * 2);
        float2 a1 = *(const float2*)(asrc + lane * 2);
        float2 a2 = *(const float2*)(adst + lane * 2);
        d1 = hv.x * a1.x + hv.y * a1.y;
        d2 = hv.x * a2.x + hv.y * a2.y;
    }
    #pragma unroll
    for (int o = 16; o; o >>= 1) {
        d1 += __shfl_xor_sync(0xffffffffu, d1, o);
        d2 += __shfl_xor_sync(0xffffffffu, d2, o);
    }
    if (lane == 0) { g_ssrc[node] = d1; g_sdst[node] = d2; }
}

// ---------------- edge score kernels ----------------
__device__ __forceinline__ void edge_decode(const int* __restrict__ ei, int t,
                                            int& src, int& dst) {
    if (t < N_EDGES) { src = ei[t]; dst = ei[N_EDGES + t]; }
    else             { src = dst = t - N_EDGES; }
}

// Layer 1: compute e, assign CSR slot, record slot for layer 2 reuse.
__global__ void k_scatter1(const int* __restrict__ ei) {
    int t = blockIdx.x * blockDim.x + threadIdx.x;
    if (t >= ETOT) return;
    int src, dst; edge_decode(ei, t, src, dst);
    float e = g_ssrc[src] + g_sdst[dst];
    e = (e > 0.f) ? e : NEG_SLOPE * e;
    int pos = g_off[dst] + atomicAdd(&g_cur[dst], 1);
    g_col[pos] = src;
    g_eval[pos] = e;
    g_slot[t] = pos;
}

// Layer 2: CSR structure fixed; just refresh eval via recorded slots.
__global__ void k_eval2(const int* __restrict__ ei) {
    int t = blockIdx.x * blockDim.x + threadIdx.x;
    if (t >= ETOT) return;
    int src, dst; edge_decode(ei, t, src, dst);
    float e = g_ssrc[src] + g_sdst[dst];
    e = (e > 0.f) ? e : NEG_SLOPE * e;
    g_eval[g_slot[t]] = e;
}

// ---------------- warp-per-dst softmax aggregation (no float atomics) ----------------
template<bool ELU>
__global__ void k_agg128(const float* __restrict__ h, const float* __restrict__ bias,
                         float* __restrict__ out) {
    int node = (blockIdx.x * blockDim.x + threadIdx.x) >> 5;
    if (node >= N_NODES) return;
    int lane = threadIdx.x & 31;
    int beg = g_off[node], end = g_off[node + 1];

    float m = -1e30f;
    for (int j = beg + lane; j < end; j += 32) m = fmaxf(m, g_eval[j]);
    #pragma unroll
    for (int o = 16; o; o >>= 1) m = fmaxf(m, __shfl_xor_sync(0xffffffffu, m, o));

    float s = 0.f;
    for (int j = beg + lane; j < end; j += 32) s += __expf(g_eval[j] - m);
    #pragma unroll
    for (int o = 16; o; o >>= 1) s += __shfl_xor_sync(0xffffffffu, s, o);
    float inv = 1.f / s;

    float4 acc = make_float4(0.f, 0.f, 0.f, 0.f);
    for (int j = beg; j < end; j++) {
        float alpha = __expf(g_eval[j] - m) * inv;
        int src = g_col[j];
        float4 hv = *(const float4*)(h + (size_t)src * 128 + lane * 4);
        acc.x = fmaf(alpha, hv.x, acc.x);
        acc.y = fmaf(alpha, hv.y, acc.y);
        acc.z = fmaf(alpha, hv.z, acc.z);
        acc.w = fmaf(alpha, hv.w, acc.w);
    }
    float4 bv = *(const float4*)(bias + lane * 4);
    acc.x += bv.x; acc.y += bv.y; acc.z += bv.z; acc.w += bv.w;
    if (ELU) {
        acc.x = (acc.x > 0.f) ? acc.x : expm1f(acc.x);
        acc.y = (acc.y > 0.f) ? acc.y : expm1f(acc.y);
        acc.z = (acc.z > 0.f) ? acc.z : expm1f(acc.z);
        acc.w = (acc.w > 0.f) ? acc.w : expm1f(acc.w);
    }
    *(float4*)(out + (size_t)node * 128 + lane * 4) = acc;
}

__global__ void k_agg64(const float* __restrict__ h, const float* __restrict__ bias,
                        float* __restrict__ out) {
    int node = (blockIdx.x * blockDim.x + threadIdx.x) >> 5;
    if (node >= N_NODES) return;
    int lane = threadIdx.x & 31;
    int beg = g_off[node], end = g_off[node + 1];

    float m = -1e30f;
    for (int j = beg + lane; j < end; j += 32) m = fmaxf(m, g_eval[j]);
    #pragma unroll
    for (int o = 16; o; o >>= 1) m = fmaxf(m, __shfl_xor_sync(0xffffffffu, m, o));

    float s = 0.f;
    for (int j = beg + lane; j < end; j += 32) s += __expf(g_eval[j] - m);
    #pragma unroll
    for (int o = 16; o; o >>= 1) s += __shfl_xor_sync(0xffffffffu, s, o);
    float inv = 1.f / s;

    float2 acc = make_float2(0.f, 0.f);
    for (int j = beg; j < end; j++) {
        float alpha = __expf(g_eval[j] - m) * inv;
        int src = g_col[j];
        float2 hv = *(const float2*)(h + (size_t)src * 64 + lane * 2);
        acc.x = fmaf(alpha, hv.x, acc.x);
        acc.y = fmaf(alpha, hv.y, acc.y);
    }
    float2 bv = *(const float2*)(bias + lane * 2);
    acc.x += bv.x; acc.y += bv.y;
    *(float2*)(out + (size_t)node * 64 + lane * 2) = acc;
}

// ---------------- launch ----------------
extern "C" void kernel_launch(void* const* d_in, const int* in_sizes, int n_in,
                              void* d_out, int out_size) {
    const float* x     = (const float*)d_in[0];
    const int*   ei    = (const int*)d_in[1];
    const float* W1    = (const float*)d_in[2];
    const float* a1s   = (const float*)d_in[3];
    const float* a1d   = (const float*)d_in[4];
    const float* b1    = (const float*)d_in[5];
    const float* W2    = (const float*)d_in[6];
    const float* a2s   = (const float*)d_in[7];
    const float* a2d   = (const float*)d_in[8];
    const float* b2    = (const float*)d_in[9];
    float* out = (float*)d_out;

    const int nodeBlk  = (N_NODES + 255) / 256;
    const int edgeBlk  = (ETOT + 255) / 256;
    const int warpBlk  = (N_NODES * 32 + 255) / 256;   // warp-per-node kernels
    const int gemmBlk  = (N_NODES + 63) / 64;

    // CSR build (structure shared by both layers)
    k_zero<<<nodeBlk, 256>>>();
    k_count<<<edgeBlk, 256>>>(ei);
    k_scan1<<<SCAN_NB, 256>>>();
    k_scan2<<<1, 512>>>(SCAN_NB);
    k_scan3<<<SCAN_NB, 256>>>();

    // Layer 1
    k_gemm<IN_DIM, HID><<<gemmBlk, 256>>>(x, W1, g_h1, N_NODES);
    k_sdot<HID><<<warpBlk, 256>>>(g_h1, a1s, a1d);
    k_scatter1<<<edgeBlk, 256>>>(ei);
    k_agg128<true><<<warpBlk, 256>>>(g_h1, b1, g_o1);

    // Layer 2
    k_gemm<HID, OUTD><<<gemmBlk, 256>>>(g_o1, W2, g_h2, N_NODES);
    k_sdot<OUTD><<<warpBlk, 256>>>(g_h2, a2s, a2d);
    k_eval2<<<edgeBlk, 256>>>(ei);
    k_agg64<<<warpBlk, 256>>>(g_h2, b2, out);
}